// round 3
// baseline (speedup 1.0000x reference)
#include <cuda_runtime.h>
#include <cstdint>
#include <cstddef>

// Shapes fixed by the reference: B=8, N=2048, F_in=F_out=128, fp32.
#define B_DIM 8
#define N_DIM 2048
#define F_DIM 128

// Scratch (device globals; no dynamic allocation allowed)
__device__ float g_deg[B_DIM * N_DIM];                    // rsqrt(1 + rowsum(adj))
__device__ float g_yt[(size_t)B_DIM * F_DIM * N_DIM];     // yt[b][f][m] = tf32( d_m * (x W^T)[m,f] )

// ---------------------------------------------------------------------------
// helpers
// ---------------------------------------------------------------------------
// round-to-nearest fp32 -> tf32; PTX requires a .b32 destination for tf32
__device__ __forceinline__ uint32_t tf32_rn(float x) {
    uint32_t r; asm("cvt.rna.tf32.f32 %0, %1;" : "=r"(r) : "f"(x)); return r;
}
__device__ __forceinline__ float tf32_rn_f(float x) {
    return __uint_as_float(tf32_rn(x));
}
__device__ __forceinline__ uint32_t smem_u32(const void* p) {
    uint32_t a;
    asm("{ .reg .u64 t; cvta.to.shared.u64 t, %1; cvt.u32.u64 %0, t; }" : "=r"(a) : "l"(p));
    return a;
}
#define CP_ASYNC16(smem, gptr) \
    asm volatile("cp.async.cg.shared.global [%0], [%1], 16;" :: "r"(smem), "l"(gptr) : "memory")
#define CP_COMMIT() asm volatile("cp.async.commit_group;" ::: "memory")
#define CP_WAIT(n)  asm volatile("cp.async.wait_group %0;" :: "n"(n) : "memory")

// D += A(16x8,row) * B(8x8,col)  tf32, fp32 accum
__device__ __forceinline__ void mma_tf32(float* c, const uint32_t* a, const uint32_t* b) {
    asm volatile(
        "mma.sync.aligned.m16n8k8.row.col.f32.tf32.tf32.f32 "
        "{%0,%1,%2,%3}, {%4,%5,%6,%7}, {%8,%9}, {%0,%1,%2,%3};"
        : "+f"(c[0]), "+f"(c[1]), "+f"(c[2]), "+f"(c[3])
        : "r"(a[0]), "r"(a[1]), "r"(a[2]), "r"(a[3]), "r"(b[0]), "r"(b[1]));
}

// ---------------------------------------------------------------------------
// Kernel 1: d[b,n] = rsqrt(1 + rowsum(adj[b,n,:]))   (warp per row, streaming)
// ---------------------------------------------------------------------------
__global__ void __launch_bounds__(256)
gcn_deg_kernel(const float* __restrict__ adj) {
    const int wid = threadIdx.x >> 5, lid = threadIdx.x & 31;
    const size_t row = (size_t)blockIdx.x * 8 + wid;                 // 16384 rows
    const float4* p = reinterpret_cast<const float4*>(adj + row * N_DIM);
    float s = 0.f;
    #pragma unroll
    for (int t = 0; t < 16; t++) {
        float4 v = p[t * 32 + lid];
        s += (v.x + v.y) + (v.z + v.w);
    }
    #pragma unroll
    for (int o = 16; o; o >>= 1) s += __shfl_xor_sync(0xFFFFFFFF, s, o);
    if (lid == 0) g_deg[row] = rsqrtf(s + 1.0f);
}

// ---------------------------------------------------------------------------
// Kernel 2: yt[b][f][m] = tf32( d[b,m] * sum_k x[b,m,k] W[f,k] )
//   128x128x128 per CTA via mma.sync, output transposed (m inner) through smem.
// ---------------------------------------------------------------------------
#define K2_PAD 132                                  // floats per smem row (conflict-free)
#define K2_SMEM (2 * 128 * K2_PAD * 4)              // 135168 B

__global__ void __launch_bounds__(128, 1)
gcn_xw_kernel(const float* __restrict__ x, const float* __restrict__ W) {
    extern __shared__ float sm[];
    float* Xs = sm;                                 // [128][K2_PAD]  rows = m, cols = k
    float* Ws = sm + 128 * K2_PAD;                  // [128][K2_PAD]  rows = f, cols = k
    const int tid = threadIdx.x, wid = tid >> 5, lane = tid & 31;
    const int b = blockIdx.y, mt = blockIdx.x;
    const float* xg = x + ((size_t)b * N_DIM + (size_t)mt * 128) * F_DIM;

    // stage + round to tf32 (RN) so the MMA unit's truncation never applies
    #pragma unroll
    for (int t = 0; t < 32; t++) {
        int idx = tid + t * 128;                    // 4096 float4 per operand
        int row = idx >> 5, c4 = (idx & 31) * 4;
        float4 v = *reinterpret_cast<const float4*>(xg + (size_t)row * F_DIM + c4);
        Xs[row * K2_PAD + c4 + 0] = tf32_rn_f(v.x);
        Xs[row * K2_PAD + c4 + 1] = tf32_rn_f(v.y);
        Xs[row * K2_PAD + c4 + 2] = tf32_rn_f(v.z);
        Xs[row * K2_PAD + c4 + 3] = tf32_rn_f(v.w);
        float4 w = *reinterpret_cast<const float4*>(W + (size_t)row * F_DIM + c4);
        Ws[row * K2_PAD + c4 + 0] = tf32_rn_f(w.x);
        Ws[row * K2_PAD + c4 + 1] = tf32_rn_f(w.y);
        Ws[row * K2_PAD + c4 + 2] = tf32_rn_f(w.z);
        Ws[row * K2_PAD + c4 + 3] = tf32_rn_f(w.w);
    }
    __syncthreads();

    const int g = lane >> 2, t4 = lane & 3;
    const int wm = (wid >> 1) * 64, wf = (wid & 1) * 64;   // 2x2 warp grid, 64x64 tiles
    float acc[4][8][4] = {};

    #pragma unroll
    for (int ks = 0; ks < 16; ks++) {
        const int k0 = ks * 8;
        uint32_t a[4][4], bb[8][2];
        #pragma unroll
        for (int i = 0; i < 4; i++) {
            const float* p = Xs + (wm + i * 16 + g) * K2_PAD + k0 + t4;
            a[i][0] = __float_as_uint(p[0]);
            a[i][1] = __float_as_uint(p[8 * K2_PAD]);
            a[i][2] = __float_as_uint(p[4]);
            a[i][3] = __float_as_uint(p[8 * K2_PAD + 4]);
        }
        #pragma unroll
        for (int j = 0; j < 8; j++) {
            const float* p = Ws + (wf + j * 8 + g) * K2_PAD + k0 + t4;
            bb[j][0] = __float_as_uint(p[0]);
            bb[j][1] = __float_as_uint(p[4]);
        }
        #pragma unroll
        for (int i = 0; i < 4; i++)
            #pragma unroll
            for (int j = 0; j < 8; j++)
                mma_tf32(acc[i][j], a[i], bb[j]);
    }
    __syncthreads();

    // transpose through smem: Cs[f][m]
    float* Cs = sm;
    #pragma unroll
    for (int i = 0; i < 4; i++) {
        int m0 = wm + i * 16 + g;
        #pragma unroll
        for (int j = 0; j < 8; j++) {
            int f0 = wf + j * 8 + 2 * t4;
            Cs[(f0    ) * K2_PAD + m0    ] = acc[i][j][0];
            Cs[(f0 + 1) * K2_PAD + m0    ] = acc[i][j][1];
            Cs[(f0    ) * K2_PAD + m0 + 8] = acc[i][j][2];
            Cs[(f0 + 1) * K2_PAD + m0 + 8] = acc[i][j][3];
        }
    }
    __syncthreads();

    const float* degp = g_deg + b * N_DIM + mt * 128;
    float* ytb = g_yt + (size_t)b * F_DIM * N_DIM + (size_t)mt * 128;
    for (int f = wid; f < 128; f += 4) {            // warp per f-row: coalesced 512B stores
        int m = lane * 4;
        float4 c = *reinterpret_cast<const float4*>(Cs + f * K2_PAD + m);
        float4 d = *reinterpret_cast<const float4*>(degp + m);
        float4 o;
        o.x = tf32_rn_f(d.x * c.x);
        o.y = tf32_rn_f(d.y * c.y);
        o.z = tf32_rn_f(d.z * c.z);
        o.w = tf32_rn_f(d.w * c.w);
        *reinterpret_cast<float4*>(ytb + (size_t)f * N_DIM + m) = o;
    }
}

// ---------------------------------------------------------------------------
// Kernel 3: out[b,n,f] = d_n * ( sum_m adj[b,n,m]*yt[b,f,m] + yt[b,f,n] ) + bias[f]
//   128x128 tile per CTA, K=2048, 4-stage cp.async multistage (prefetch dist 3).
// ---------------------------------------------------------------------------
#define K3_PAD 36                                   // floats per smem row (chunk k=32)
#define K3_ATILE (128 * K3_PAD)                     // floats per operand tile
#define K3_STAGE (2 * K3_ATILE)                     // floats per stage (A + B)
#define K3_SMEM (4 * K3_STAGE * 4)                  // 147456 B

__global__ void __launch_bounds__(128, 1)
gcn_agg_kernel(const float* __restrict__ adj, const float* __restrict__ bias,
               float* __restrict__ out) {
    extern __shared__ float sm[];
    const uint32_t sb = smem_u32(sm);
    const int tid = threadIdx.x, lane = tid & 31, wid = tid >> 5;
    const int b = blockIdx.y, ntile = blockIdx.x;
    const float* Ag = adj  + ((size_t)b * N_DIM + (size_t)ntile * 128) * N_DIM;  // [128n x 2048m]
    const float* Bg = g_yt + (size_t)b * F_DIM * N_DIM;                           // [128f x 2048m]

    #define K3_FILL(stage, chunk) do {                                            \
        uint32_t sa_ = sb + (stage) * (K3_STAGE * 4);                             \
        uint32_t sbm_ = sa_ + (K3_ATILE * 4);                                     \
        const float* Ac_ = Ag + (chunk) * 32;                                     \
        const float* Bc_ = Bg + (chunk) * 32;                                     \
        _Pragma("unroll")                                                         \
        for (int t_ = 0; t_ < 8; t_++) {                                          \
            int idx_ = tid + t_ * 128;                                            \
            int row_ = idx_ >> 3, c4_ = idx_ & 7;                                 \
            uint32_t so_ = (uint32_t)row_ * (K3_PAD * 4) + (uint32_t)c4_ * 16;    \
            CP_ASYNC16(sa_  + so_, Ac_ + (size_t)row_ * N_DIM + c4_ * 4);         \
            CP_ASYNC16(sbm_ + so_, Bc_ + (size_t)row_ * N_DIM + c4_ * 4);         \
        }                                                                         \
        CP_COMMIT();                                                              \
    } while (0)

    K3_FILL(0, 0); K3_FILL(1, 1); K3_FILL(2, 2);

    const int g = lane >> 2, t4 = lane & 3;
    const int wn = (wid >> 1) * 64, wf = (wid & 1) * 64;   // 2x2 warps, 64x64 tiles
    float acc[4][8][4] = {};

    for (int i = 0; i < 64; i++) {
        if (i < 62)      CP_WAIT(2);
        else if (i == 62) CP_WAIT(1);
        else              CP_WAIT(0);
        __syncthreads();                            // chunk i resident; stage (i-1)&3 free
        if (i + 3 < 64) K3_FILL((i + 3) & 3, i + 3);

        const float* As = sm + (size_t)(i & 3) * K3_STAGE;
        const float* Bs = As + K3_ATILE;
        #pragma unroll
        for (int ks = 0; ks < 4; ks++) {
            const int k0 = ks * 8;
            uint32_t a[4][4], bb[8][2];
            #pragma unroll
            for (int m_ = 0; m_ < 4; m_++) {        // adj frags: round RN to tf32
                const float* p = As + (wn + m_ * 16 + g) * K3_PAD + k0 + t4;
                a[m_][0] = tf32_rn(p[0]);
                a[m_][1] = tf32_rn(p[8 * K3_PAD]);
                a[m_][2] = tf32_rn(p[4]);
                a[m_][3] = tf32_rn(p[8 * K3_PAD + 4]);
            }
            #pragma unroll
            for (int n_ = 0; n_ < 8; n_++) {        // yt already tf32-rounded
                const float* p = Bs + (wf + n_ * 8 + g) * K3_PAD + k0 + t4;
                bb[n_][0] = __float_as_uint(p[0]);
                bb[n_][1] = __float_as_uint(p[4]);
            }
            #pragma unroll
            for (int m_ = 0; m_ < 4; m_++)
                #pragma unroll
                for (int n_ = 0; n_ < 8; n_++)
                    mma_tf32(acc[m_][n_], a[m_], bb[n_]);
        }
    }

    // epilogue: scale + self-loop + bias, float2 stores (32B-sector aligned)
    const int nbase = ntile * 128;
    #pragma unroll
    for (int m_ = 0; m_ < 4; m_++) {
        const int n0 = wn + m_ * 16 + g;
        const float dn0 = g_deg[b * N_DIM + nbase + n0];
        const float dn1 = g_deg[b * N_DIM + nbase + n0 + 8];
        #pragma unroll
        for (int n_ = 0; n_ < 8; n_++) {
            const int f0 = wf + n_ * 8 + 2 * t4;
            const float bi0 = bias[f0], bi1 = bias[f0 + 1];
            const float s00 = Bg[(size_t)(f0    ) * N_DIM + nbase + n0];
            const float s10 = Bg[(size_t)(f0 + 1) * N_DIM + nbase + n0];
            const float s01 = Bg[(size_t)(f0    ) * N_DIM + nbase + n0 + 8];
            const float s11 = Bg[(size_t)(f0 + 1) * N_DIM + nbase + n0 + 8];
            float2 v0, v1;
            v0.x = dn0 * (acc[m_][n_][0] + s00) + bi0;
            v0.y = dn0 * (acc[m_][n_][1] + s10) + bi1;
            v1.x = dn1 * (acc[m_][n_][2] + s01) + bi0;
            v1.y = dn1 * (acc[m_][n_][3] + s11) + bi1;
            *reinterpret_cast<float2*>(out + ((size_t)b * N_DIM + nbase + n0    ) * F_DIM + f0) = v0;
            *reinterpret_cast<float2*>(out + ((size_t)b * N_DIM + nbase + n0 + 8) * F_DIM + f0) = v1;
        }
    }
}

// ---------------------------------------------------------------------------
extern "C" void kernel_launch(void* const* d_in, const int* in_sizes, int n_in,
                              void* d_out, int out_size) {
    const float* x    = (const float*)d_in[0];   // [8,2048,128]
    const float* adj  = (const float*)d_in[1];   // [8,2048,2048]
    const float* W    = (const float*)d_in[2];   // [128,128]
    const float* bias = (const float*)d_in[3];   // [128]
    float* out = (float*)d_out;                  // [8,2048,128]

    cudaFuncSetAttribute(gcn_xw_kernel,  cudaFuncAttributeMaxDynamicSharedMemorySize, K2_SMEM);
    cudaFuncSetAttribute(gcn_agg_kernel, cudaFuncAttributeMaxDynamicSharedMemorySize, K3_SMEM);

    gcn_deg_kernel<<<(B_DIM * N_DIM) / 8, 256>>>(adj);
    gcn_xw_kernel<<<dim3(N_DIM / 128, B_DIM), 128, K2_SMEM>>>(x, W);
    gcn_agg_kernel<<<dim3(N_DIM / 128, B_DIM), 128, K3_SMEM>>>(adj, bias, out);
}

// round 4
// speedup vs baseline: 1.0153x; 1.0153x over previous
#include <cuda_runtime.h>
#include <cstdint>
#include <cstddef>

// Shapes fixed by the reference: B=8, N=2048, F_in=F_out=128, fp32.
#define B_DIM 8
#define N_DIM 2048
#define F_DIM 128

// Scratch (device globals; no dynamic allocation allowed)
__device__ float g_deg[B_DIM * N_DIM];                    // rsqrt(1 + rowsum(adj))
__device__ float g_yt[(size_t)B_DIM * F_DIM * N_DIM];     // yt[b][f][m] = tf32( d_m * (x W^T)[m,f] )

// ---------------------------------------------------------------------------
// helpers
// ---------------------------------------------------------------------------
__device__ __forceinline__ uint32_t tf32_rn(float x) {    // fp32 -> tf32 (RN), .b32 dst
    uint32_t r; asm("cvt.rna.tf32.f32 %0, %1;" : "=r"(r) : "f"(x)); return r;
}
__device__ __forceinline__ float tf32_rn_f(float x) {
    return __uint_as_float(tf32_rn(x));
}
__device__ __forceinline__ uint32_t smem_u32(const void* p) {
    uint32_t a;
    asm("{ .reg .u64 t; cvta.to.shared.u64 t, %1; cvt.u32.u64 %0, t; }" : "=r"(a) : "l"(p));
    return a;
}
#define CP_ASYNC16(smem, gptr) \
    asm volatile("cp.async.cg.shared.global [%0], [%1], 16;" :: "r"(smem), "l"(gptr) : "memory")
#define CP_COMMIT() asm volatile("cp.async.commit_group;" ::: "memory")
#define CP_WAIT(n)  asm volatile("cp.async.wait_group %0;" :: "n"(n) : "memory")

// D += A(16x8,row) * B(8x8,col)  tf32, fp32 accum
__device__ __forceinline__ void mma_tf32(float* c, const uint32_t* a, const uint32_t* b) {
    asm volatile(
        "mma.sync.aligned.m16n8k8.row.col.f32.tf32.tf32.f32 "
        "{%0,%1,%2,%3}, {%4,%5,%6,%7}, {%8,%9}, {%0,%1,%2,%3};"
        : "+f"(c[0]), "+f"(c[1]), "+f"(c[2]), "+f"(c[3])
        : "r"(a[0]), "r"(a[1]), "r"(a[2]), "r"(a[3]), "r"(b[0]), "r"(b[1]));
}

// ---------------------------------------------------------------------------
// Kernel 1: d[b,n] = rsqrt(1 + rowsum(adj[b,n,:]))   (warp per row, streaming)
// ---------------------------------------------------------------------------
__global__ void __launch_bounds__(256)
gcn_deg_kernel(const float* __restrict__ adj) {
    const int wid = threadIdx.x >> 5, lid = threadIdx.x & 31;
    const size_t row = (size_t)blockIdx.x * 8 + wid;                 // 16384 rows
    const float4* p = reinterpret_cast<const float4*>(adj + row * N_DIM);
    float s = 0.f;
    #pragma unroll
    for (int t = 0; t < 16; t++) {
        float4 v = p[t * 32 + lid];
        s += (v.x + v.y) + (v.z + v.w);
    }
    #pragma unroll
    for (int o = 16; o; o >>= 1) s += __shfl_xor_sync(0xFFFFFFFF, s, o);
    if (lid == 0) g_deg[row] = rsqrtf(s + 1.0f);
}

// ---------------------------------------------------------------------------
// Kernel 2: yt[b][f][m] = tf32( d[b,m] * sum_k x[b,m,k] W[f,k] )
// ---------------------------------------------------------------------------
#define K2_PAD 132
#define K2_SMEM (2 * 128 * K2_PAD * 4)

__global__ void __launch_bounds__(128, 1)
gcn_xw_kernel(const float* __restrict__ x, const float* __restrict__ W) {
    extern __shared__ float sm[];
    float* Xs = sm;                                 // [128][K2_PAD]  rows = m
    float* Ws = sm + 128 * K2_PAD;                  // [128][K2_PAD]  rows = f
    const int tid = threadIdx.x, wid = tid >> 5, lane = tid & 31;
    const int b = blockIdx.y, mt = blockIdx.x;
    const float* xg = x + ((size_t)b * N_DIM + (size_t)mt * 128) * F_DIM;

    #pragma unroll
    for (int t = 0; t < 32; t++) {
        int idx = tid + t * 128;
        int row = idx >> 5, c4 = (idx & 31) * 4;
        float4 v = *reinterpret_cast<const float4*>(xg + (size_t)row * F_DIM + c4);
        Xs[row * K2_PAD + c4 + 0] = tf32_rn_f(v.x);
        Xs[row * K2_PAD + c4 + 1] = tf32_rn_f(v.y);
        Xs[row * K2_PAD + c4 + 2] = tf32_rn_f(v.z);
        Xs[row * K2_PAD + c4 + 3] = tf32_rn_f(v.w);
        float4 w = *reinterpret_cast<const float4*>(W + (size_t)row * F_DIM + c4);
        Ws[row * K2_PAD + c4 + 0] = tf32_rn_f(w.x);
        Ws[row * K2_PAD + c4 + 1] = tf32_rn_f(w.y);
        Ws[row * K2_PAD + c4 + 2] = tf32_rn_f(w.z);
        Ws[row * K2_PAD + c4 + 3] = tf32_rn_f(w.w);
    }
    __syncthreads();

    const int g = lane >> 2, t4 = lane & 3;
    const int wm = (wid >> 1) * 64, wf = (wid & 1) * 64;
    float acc[4][8][4] = {};

    #pragma unroll
    for (int ks = 0; ks < 16; ks++) {
        const int k0 = ks * 8;
        uint32_t a[4][4], bb[8][2];
        #pragma unroll
        for (int i = 0; i < 4; i++) {
            const float* p = Xs + (wm + i * 16 + g) * K2_PAD + k0 + t4;
            a[i][0] = __float_as_uint(p[0]);
            a[i][1] = __float_as_uint(p[8 * K2_PAD]);
            a[i][2] = __float_as_uint(p[4]);
            a[i][3] = __float_as_uint(p[8 * K2_PAD + 4]);
        }
        #pragma unroll
        for (int j = 0; j < 8; j++) {
            const float* p = Ws + (wf + j * 8 + g) * K2_PAD + k0 + t4;
            bb[j][0] = __float_as_uint(p[0]);
            bb[j][1] = __float_as_uint(p[4]);
        }
        #pragma unroll
        for (int i = 0; i < 4; i++)
            #pragma unroll
            for (int j = 0; j < 8; j++)
                mma_tf32(acc[i][j], a[i], bb[j]);
    }
    __syncthreads();

    float* Cs = sm;                                 // transpose: Cs[f][m]
    #pragma unroll
    for (int i = 0; i < 4; i++) {
        int m0 = wm + i * 16 + g;
        #pragma unroll
        for (int j = 0; j < 8; j++) {
            int f0 = wf + j * 8 + 2 * t4;
            Cs[(f0    ) * K2_PAD + m0    ] = acc[i][j][0];
            Cs[(f0 + 1) * K2_PAD + m0    ] = acc[i][j][1];
            Cs[(f0    ) * K2_PAD + m0 + 8] = acc[i][j][2];
            Cs[(f0 + 1) * K2_PAD + m0 + 8] = acc[i][j][3];
        }
    }
    __syncthreads();

    const float* degp = g_deg + b * N_DIM + mt * 128;
    float* ytb = g_yt + (size_t)b * F_DIM * N_DIM + (size_t)mt * 128;
    for (int f = wid; f < 128; f += 4) {
        int m = lane * 4;
        float4 c = *reinterpret_cast<const float4*>(Cs + f * K2_PAD + m);
        float4 d = *reinterpret_cast<const float4*>(degp + m);
        float4 o;
        o.x = tf32_rn_f(d.x * c.x);
        o.y = tf32_rn_f(d.y * c.y);
        o.z = tf32_rn_f(d.z * c.z);
        o.w = tf32_rn_f(d.w * c.w);
        *reinterpret_cast<float4*>(ytb + (size_t)f * N_DIM + m) = o;
    }
}

// ---------------------------------------------------------------------------
// Kernel 3: out[b,n,f] = d_n * ( sum_m adj[b,n,m]*yt[b,f,m] + yt[b,f,n] ) + bias[f]
//   256 threads, 2 teams of 4 warps: team 0 = even K-chunks, team 1 = odd.
//   4 chunk-slots in smem, fills in chunk-pairs (one commit group per pair).
// ---------------------------------------------------------------------------
#define K3_PAD 36
#define K3_ATILE (128 * K3_PAD)
#define K3_STAGE (2 * K3_ATILE)                     // one chunk-slot (A+B)
#define K3_SMEM (4 * K3_STAGE * 4)                  // 147456 B
#define K3_RPAD 132                                 // reduction buffer row stride

__global__ void __launch_bounds__(256, 1)
gcn_agg_kernel(const float* __restrict__ adj, const float* __restrict__ bias,
               float* __restrict__ out) {
    extern __shared__ float sm[];
    const uint32_t sb = smem_u32(sm);
    const int tid = threadIdx.x, lane = tid & 31, wid = tid >> 5;
    const int team = wid >> 2, wid2 = wid & 3;
    const int b = blockIdx.y, ntile = blockIdx.x;
    const float* Ag = adj  + ((size_t)b * N_DIM + (size_t)ntile * 128) * N_DIM;  // [128n x 2048m]
    const float* Bg = g_yt + (size_t)b * F_DIM * N_DIM;                           // [128f x 2048m]

    // cooperative fill of one chunk (256 threads, 4 float4 per operand each)
    #define K3_FILLC(chunk) do {                                                  \
        uint32_t sa_ = sb + ((chunk) & 3) * (K3_STAGE * 4);                       \
        uint32_t sbm_ = sa_ + (K3_ATILE * 4);                                     \
        const float* Ac_ = Ag + (chunk) * 32;                                     \
        const float* Bc_ = Bg + (chunk) * 32;                                     \
        _Pragma("unroll")                                                         \
        for (int t_ = 0; t_ < 4; t_++) {                                          \
            int idx_ = tid + t_ * 256;                                            \
            int row_ = idx_ >> 3, c4_ = idx_ & 7;                                 \
            uint32_t so_ = (uint32_t)row_ * (K3_PAD * 4) + (uint32_t)c4_ * 16;    \
            CP_ASYNC16(sa_  + so_, Ac_ + (size_t)row_ * N_DIM + c4_ * 4);         \
            CP_ASYNC16(sbm_ + so_, Bc_ + (size_t)row_ * N_DIM + c4_ * 4);         \
        }                                                                         \
    } while (0)

    K3_FILLC(0); K3_FILLC(1); CP_COMMIT();          // pair 0
    K3_FILLC(2); K3_FILLC(3); CP_COMMIT();          // pair 1

    const int g = lane >> 2, t4 = lane & 3;
    const int wn = (wid2 >> 1) * 64, wf = (wid2 & 1) * 64;   // 2x2 warps per team
    float acc[4][8][4] = {};

    for (int p = 0; p < 32; p++) {                  // pair p = chunks {2p, 2p+1}
        if (p < 31) CP_WAIT(1); else CP_WAIT(0);
        __syncthreads();                            // pair p resident for everyone

        const int chunk = 2 * p + team;             // team-parallel MMA
        const float* As = sm + (size_t)(chunk & 3) * K3_STAGE;
        const float* Bs = As + K3_ATILE;
        #pragma unroll
        for (int ks = 0; ks < 4; ks++) {
            const int k0 = ks * 8;
            uint32_t a[4][4], bb[8][2];
            #pragma unroll
            for (int m_ = 0; m_ < 4; m_++) {        // adj frags: round RN to tf32
                const float* q = As + (wn + m_ * 16 + g) * K3_PAD + k0 + t4;
                a[m_][0] = tf32_rn(q[0]);
                a[m_][1] = tf32_rn(q[8 * K3_PAD]);
                a[m_][2] = tf32_rn(q[4]);
                a[m_][3] = tf32_rn(q[8 * K3_PAD + 4]);
            }
            #pragma unroll
            for (int n_ = 0; n_ < 8; n_++) {        // yt already tf32-rounded
                const float* q = Bs + (wf + n_ * 8 + g) * K3_PAD + k0 + t4;
                bb[n_][0] = __float_as_uint(q[0]);
                bb[n_][1] = __float_as_uint(q[4]);
            }
            #pragma unroll
            for (int m_ = 0; m_ < 4; m_++)
                #pragma unroll
                for (int n_ = 0; n_ < 8; n_++)
                    mma_tf32(acc[m_][n_], a[m_], bb[n_]);
        }

        __syncthreads();                            // both teams done with pair p slots
        if (p + 2 < 32) {                           // refill those slots with pair p+2
            K3_FILLC(2 * p + 4); K3_FILLC(2 * p + 5); CP_COMMIT();
        }
    }

    // cross-team reduction: team 1 dumps partials, team 0 adds + epilogue
    __syncthreads();
    float* Cs = sm;                                 // [128][K3_RPAD] (reuses pipeline smem)
    if (team == 1) {
        #pragma unroll
        for (int m_ = 0; m_ < 4; m_++) {
            const int n0 = wn + m_ * 16 + g;
            #pragma unroll
            for (int n_ = 0; n_ < 8; n_++) {
                const int f0 = wf + n_ * 8 + 2 * t4;
                Cs[(n0    ) * K3_RPAD + f0    ] = acc[m_][n_][0];
                Cs[(n0    ) * K3_RPAD + f0 + 1] = acc[m_][n_][1];
                Cs[(n0 + 8) * K3_RPAD + f0    ] = acc[m_][n_][2];
                Cs[(n0 + 8) * K3_RPAD + f0 + 1] = acc[m_][n_][3];
            }
        }
    }
    __syncthreads();

    if (team == 0) {
        const int nbase = ntile * 128;
        #pragma unroll
        for (int m_ = 0; m_ < 4; m_++) {
            const int n0 = wn + m_ * 16 + g;
            const float dn0 = g_deg[b * N_DIM + nbase + n0];
            const float dn1 = g_deg[b * N_DIM + nbase + n0 + 8];
            #pragma unroll
            for (int n_ = 0; n_ < 8; n_++) {
                const int f0 = wf + n_ * 8 + 2 * t4;
                const float bi0 = bias[f0], bi1 = bias[f0 + 1];
                const float p00 = acc[m_][n_][0] + Cs[(n0    ) * K3_RPAD + f0    ];
                const float p10 = acc[m_][n_][1] + Cs[(n0    ) * K3_RPAD + f0 + 1];
                const float p01 = acc[m_][n_][2] + Cs[(n0 + 8) * K3_RPAD + f0    ];
                const float p11 = acc[m_][n_][3] + Cs[(n0 + 8) * K3_RPAD + f0 + 1];
                const float s00 = Bg[(size_t)(f0    ) * N_DIM + nbase + n0];
                const float s10 = Bg[(size_t)(f0 + 1) * N_DIM + nbase + n0];
                const float s01 = Bg[(size_t)(f0    ) * N_DIM + nbase + n0 + 8];
                const float s11 = Bg[(size_t)(f0 + 1) * N_DIM + nbase + n0 + 8];
                float2 v0, v1;
                v0.x = dn0 * (p00 + s00) + bi0;
                v0.y = dn0 * (p10 + s10) + bi1;
                v1.x = dn1 * (p01 + s01) + bi0;
                v1.y = dn1 * (p11 + s11) + bi1;
                *reinterpret_cast<float2*>(out + ((size_t)b * N_DIM + nbase + n0    ) * F_DIM + f0) = v0;
                *reinterpret_cast<float2*>(out + ((size_t)b * N_DIM + nbase + n0 + 8) * F_DIM + f0) = v1;
            }
        }
    }
}

// ---------------------------------------------------------------------------
extern "C" void kernel_launch(void* const* d_in, const int* in_sizes, int n_in,
                              void* d_out, int out_size) {
    const float* x    = (const float*)d_in[0];   // [8,2048,128]
    const float* adj  = (const float*)d_in[1];   // [8,2048,2048]
    const float* W    = (const float*)d_in[2];   // [128,128]
    const float* bias = (const float*)d_in[3];   // [128]
    float* out = (float*)d_out;                  // [8,2048,128]

    cudaFuncSetAttribute(gcn_xw_kernel,  cudaFuncAttributeMaxDynamicSharedMemorySize, K2_SMEM);
    cudaFuncSetAttribute(gcn_agg_kernel, cudaFuncAttributeMaxDynamicSharedMemorySize, K3_SMEM);

    gcn_deg_kernel<<<(B_DIM * N_DIM) / 8, 256>>>(adj);
    gcn_xw_kernel<<<dim3(N_DIM / 128, B_DIM), 128, K2_SMEM>>>(x, W);
    gcn_agg_kernel<<<dim3(N_DIM / 128, B_DIM), 256, K3_SMEM>>>(adj, bias, out);
}

// round 5
// speedup vs baseline: 1.1568x; 1.1394x over previous
#include <cuda_runtime.h>
#include <cstdint>
#include <cstddef>

// Shapes fixed by the reference: B=8, N=2048, F_in=F_out=128, fp32.
#define B_DIM 8
#define N_DIM 2048
#define F_DIM 128

// Scratch (device globals; no dynamic allocation allowed)
__device__ float g_deg[B_DIM * N_DIM];                    // rsqrt(1 + rowsum(adj))
__device__ float g_ys[(size_t)B_DIM * N_DIM * F_DIM];     // ys[b][m][f] = tf32( d_m * (x W^T)[m,f] )

// ---------------------------------------------------------------------------
// helpers
// ---------------------------------------------------------------------------
__device__ __forceinline__ uint32_t tf32_rn(float x) {    // fp32 -> tf32 (RN), .b32 dst
    uint32_t r; asm("cvt.rna.tf32.f32 %0, %1;" : "=r"(r) : "f"(x)); return r;
}
__device__ __forceinline__ float tf32_rn_f(float x) {
    return __uint_as_float(tf32_rn(x));
}
__device__ __forceinline__ uint32_t smem_u32(const void* p) {
    uint32_t a;
    asm("{ .reg .u64 t; cvta.to.shared.u64 t, %1; cvt.u32.u64 %0, t; }" : "=r"(a) : "l"(p));
    return a;
}
#define CP_ASYNC16(smem, gptr) \
    asm volatile("cp.async.cg.shared.global [%0], [%1], 16;" :: "r"(smem), "l"(gptr) : "memory")
#define CP_COMMIT() asm volatile("cp.async.commit_group;" ::: "memory")
#define CP_WAIT(n)  asm volatile("cp.async.wait_group %0;" :: "n"(n) : "memory")
#define BAR_TEAM(id) asm volatile("bar.sync %0, 128;" :: "r"(id) : "memory")

// D += A(16x8,row) * B(8x8,col)  tf32, fp32 accum
__device__ __forceinline__ void mma_tf32(float* c, const uint32_t* a, const uint32_t* b) {
    asm volatile(
        "mma.sync.aligned.m16n8k8.row.col.f32.tf32.tf32.f32 "
        "{%0,%1,%2,%3}, {%4,%5,%6,%7}, {%8,%9}, {%0,%1,%2,%3};"
        : "+f"(c[0]), "+f"(c[1]), "+f"(c[2]), "+f"(c[3])
        : "r"(a[0]), "r"(a[1]), "r"(a[2]), "r"(a[3]), "r"(b[0]), "r"(b[1]));
}

// ---------------------------------------------------------------------------
// Kernel 1: d[b,n] = rsqrt(1 + rowsum(adj[b,n,:]))   (warp per row, streaming)
// ---------------------------------------------------------------------------
__global__ void __launch_bounds__(256)
gcn_deg_kernel(const float* __restrict__ adj) {
    const int wid = threadIdx.x >> 5, lid = threadIdx.x & 31;
    const size_t row = (size_t)blockIdx.x * 8 + wid;                 // 16384 rows
    const float4* p = reinterpret_cast<const float4*>(adj + row * N_DIM);
    float s = 0.f;
    #pragma unroll
    for (int t = 0; t < 16; t++) {
        float4 v = p[t * 32 + lid];
        s += (v.x + v.y) + (v.z + v.w);
    }
    #pragma unroll
    for (int o = 16; o; o >>= 1) s += __shfl_xor_sync(0xFFFFFFFF, s, o);
    if (lid == 0) g_deg[row] = rsqrtf(s + 1.0f);
}

// ---------------------------------------------------------------------------
// Kernel 2: ys[b][m][f] = tf32( d[b,m] * sum_k x[b,m,k] W[f,k] )  (natural layout,
//   no transpose phase — direct register->gmem epilogue)
// ---------------------------------------------------------------------------
#define K2_PAD 132
#define K2_SMEM (2 * 128 * K2_PAD * 4)

__global__ void __launch_bounds__(128, 1)
gcn_xw_kernel(const float* __restrict__ x, const float* __restrict__ W) {
    extern __shared__ float sm[];
    float* Xs = sm;                                 // [128 m][K2_PAD]
    float* Ws = sm + 128 * K2_PAD;                  // [128 f][K2_PAD]
    const int tid = threadIdx.x, wid = tid >> 5, lane = tid & 31;
    const int b = blockIdx.y, mt = blockIdx.x;
    const float* xg = x + ((size_t)b * N_DIM + (size_t)mt * 128) * F_DIM;

    #pragma unroll
    for (int t = 0; t < 32; t++) {
        int idx = tid + t * 128;
        int row = idx >> 5, c4 = (idx & 31) * 4;
        float4 v = *reinterpret_cast<const float4*>(xg + (size_t)row * F_DIM + c4);
        Xs[row * K2_PAD + c4 + 0] = tf32_rn_f(v.x);
        Xs[row * K2_PAD + c4 + 1] = tf32_rn_f(v.y);
        Xs[row * K2_PAD + c4 + 2] = tf32_rn_f(v.z);
        Xs[row * K2_PAD + c4 + 3] = tf32_rn_f(v.w);
        float4 w = *reinterpret_cast<const float4*>(W + (size_t)row * F_DIM + c4);
        Ws[row * K2_PAD + c4 + 0] = tf32_rn_f(w.x);
        Ws[row * K2_PAD + c4 + 1] = tf32_rn_f(w.y);
        Ws[row * K2_PAD + c4 + 2] = tf32_rn_f(w.z);
        Ws[row * K2_PAD + c4 + 3] = tf32_rn_f(w.w);
    }
    __syncthreads();

    const int g = lane >> 2, t4 = lane & 3;
    const int wm = (wid >> 1) * 64, wf = (wid & 1) * 64;
    float acc[4][8][4] = {};

    #pragma unroll
    for (int ks = 0; ks < 16; ks++) {
        const int k0 = ks * 8;
        uint32_t a[4][4], bb[8][2];
        #pragma unroll
        for (int i = 0; i < 4; i++) {
            const float* p = Xs + (wm + i * 16 + g) * K2_PAD + k0 + t4;
            a[i][0] = __float_as_uint(p[0]);
            a[i][1] = __float_as_uint(p[8 * K2_PAD]);
            a[i][2] = __float_as_uint(p[4]);
            a[i][3] = __float_as_uint(p[8 * K2_PAD + 4]);
        }
        #pragma unroll
        for (int j = 0; j < 8; j++) {
            const float* p = Ws + (wf + j * 8 + g) * K2_PAD + k0 + t4;
            bb[j][0] = __float_as_uint(p[0]);
            bb[j][1] = __float_as_uint(p[4]);
        }
        #pragma unroll
        for (int i = 0; i < 4; i++)
            #pragma unroll
            for (int j = 0; j < 8; j++)
                mma_tf32(acc[i][j], a[i], bb[j]);
    }

    // direct epilogue: scale by d_m, round, store natural [m][f] (float2)
    float* yb = g_ys + ((size_t)b * N_DIM + (size_t)mt * 128) * F_DIM;
    #pragma unroll
    for (int i = 0; i < 4; i++) {
        const int m0 = wm + i * 16 + g;
        const float dm0 = g_deg[b * N_DIM + mt * 128 + m0];
        const float dm1 = g_deg[b * N_DIM + mt * 128 + m0 + 8];
        #pragma unroll
        for (int j = 0; j < 8; j++) {
            const int f0 = wf + j * 8 + 2 * t4;
            float2 v0, v1;
            v0.x = tf32_rn_f(dm0 * acc[i][j][0]);
            v0.y = tf32_rn_f(dm0 * acc[i][j][1]);
            v1.x = tf32_rn_f(dm1 * acc[i][j][2]);
            v1.y = tf32_rn_f(dm1 * acc[i][j][3]);
            *reinterpret_cast<float2*>(yb + (size_t)m0 * F_DIM + f0) = v0;
            *reinterpret_cast<float2*>(yb + (size_t)(m0 + 8) * F_DIM + f0) = v1;
        }
    }
}

// ---------------------------------------------------------------------------
// Kernel 3: out[b,n,f] = d_n * ( sum_m adj[b,n,m]*ys[m,f] + ys[n,f] ) + bias[f]
//   2 independent 4-warp teams (even/odd K-chunks), each with a PRIVATE 3-slot
//   cp.async pipeline + named team barrier. Packed swizzled tiles, 32KB/slot.
// ---------------------------------------------------------------------------
#define K3_SLOT_B 32768                             // A tile 16KB + B tile 16KB
#define K3_SMEM  (6 * K3_SLOT_B)                    // 196608 B
#define K3_RPAD  132                                // reduction buffer row stride

__global__ void __launch_bounds__(256, 1)
gcn_agg_kernel(const float* __restrict__ adj, const float* __restrict__ bias,
               float* __restrict__ out) {
    extern __shared__ float sm[];
    const uint32_t sb = smem_u32(sm);
    const int tid = threadIdx.x, lane = tid & 31, wid = tid >> 5;
    const int team = wid >> 2, wid2 = wid & 3, tt = tid & 127;
    const int b = blockIdx.y, ntile = blockIdx.x;
    const float* Ag = adj  + ((size_t)b * N_DIM + (size_t)ntile * 128) * N_DIM;  // [128n x 2048m]
    const float* Yb = g_ys + (size_t)b * N_DIM * F_DIM;                           // [2048m x 128f]

    // fill team-slot s with chunk c (team threads only; swizzled packed tiles)
    #define K3_FILL(s, c) do {                                                    \
        uint32_t abase_ = sb + (uint32_t)(team * 3 + (s)) * K3_SLOT_B;            \
        uint32_t bbase_ = abase_ + 16384;                                         \
        const float* Ac_ = Ag + (c) * 32;                                         \
        const float* Bc_ = Yb + (size_t)(c) * 32 * F_DIM;                         \
        _Pragma("unroll")                                                         \
        for (int t_ = 0; t_ < 8; t_++) {                                          \
            int idx_ = tt + t_ * 128;                                             \
            int ar_ = idx_ >> 3, ac_ = idx_ & 7;                                  \
            CP_ASYNC16(abase_ + (uint32_t)ar_ * 128 + (uint32_t)((ac_ ^ (ar_ & 7)) << 4), \
                       Ac_ + (size_t)ar_ * N_DIM + ac_ * 4);                      \
            int bm_ = idx_ >> 5, bc_ = idx_ & 31;                                 \
            CP_ASYNC16(bbase_ + (uint32_t)bm_ * 512 + (uint32_t)((bc_ ^ ((bm_ & 3) << 1)) << 4), \
                       Bc_ + (size_t)bm_ * F_DIM + bc_ * 4);                      \
        }                                                                         \
        CP_COMMIT();                                                              \
    } while (0)

    // prologue: this team's chunks 0,1 (global chunks team, team+2)
    K3_FILL(0, team);
    K3_FILL(1, team + 2);

    const int g = lane >> 2, t4 = lane & 3;
    const int wn = (wid2 >> 1) * 64, wf = (wid2 & 1) * 64;   // 2x2 warps per team
    float acc[4][8][4] = {};

    for (int i = 0; i < 32; i++) {                  // team chunk ordinal; global = 2i+team
        if (i < 31) CP_WAIT(1); else CP_WAIT(0);
        BAR_TEAM(team + 1);                         // team-chunk i resident for this team
        if (i + 2 < 32) K3_FILL((i + 2) % 3, 2 * (i + 2) + team);  // slot (i-1)%3: free

        const float* As = sm + (size_t)(team * 3 + i % 3) * (K3_SLOT_B / 4);
        const float* Bs = As + 4096;
        #pragma unroll
        for (int ks = 0; ks < 4; ks++) {
            const int k0 = ks * 8, c0 = k0 >> 2;
            uint32_t a[4][4], bb[8][2];
            #pragma unroll
            for (int m_ = 0; m_ < 4; m_++) {        // adj frags: RN-round to tf32
                const int r = wn + m_ * 16 + g;
                const int sw0 = (c0 ^ (r & 7)) << 2, sw1 = ((c0 + 1) ^ (r & 7)) << 2;
                a[m_][0] = tf32_rn(As[r * 32 + sw0 + t4]);
                a[m_][1] = tf32_rn(As[(r + 8) * 32 + sw0 + t4]);
                a[m_][2] = tf32_rn(As[r * 32 + sw1 + t4]);
                a[m_][3] = tf32_rn(As[(r + 8) * 32 + sw1 + t4]);
            }
            const int km = k0 + t4, bsw = (km & 3) << 1;
            #pragma unroll
            for (int n_ = 0; n_ < 8; n_++) {        // ys already tf32-rounded
                const int f = wf + n_ * 8 + g;
                const int col = (((f >> 2) ^ bsw) << 2) + (f & 3);
                bb[n_][0] = __float_as_uint(Bs[km * 128 + col]);
                bb[n_][1] = __float_as_uint(Bs[(km + 4) * 128 + col]);
            }
            #pragma unroll
            for (int m_ = 0; m_ < 4; m_++)
                #pragma unroll
                for (int n_ = 0; n_ < 8; n_++)
                    mma_tf32(acc[m_][n_], a[m_], bb[n_]);
        }
    }

    // cross-team reduction: team 1 dumps partials, team 0 adds + epilogue
    __syncthreads();                                // teams done; safe to reuse slots
    float* Cs = sm;                                 // [128][K3_RPAD]
    if (team == 1) {
        #pragma unroll
        for (int m_ = 0; m_ < 4; m_++) {
            const int n0 = wn + m_ * 16 + g;
            #pragma unroll
            for (int n_ = 0; n_ < 8; n_++) {
                const int f0 = wf + n_ * 8 + 2 * t4;
                Cs[(n0    ) * K3_RPAD + f0    ] = acc[m_][n_][0];
                Cs[(n0    ) * K3_RPAD + f0 + 1] = acc[m_][n_][1];
                Cs[(n0 + 8) * K3_RPAD + f0    ] = acc[m_][n_][2];
                Cs[(n0 + 8) * K3_RPAD + f0 + 1] = acc[m_][n_][3];
            }
        }
    }
    __syncthreads();

    if (team == 0) {
        const int nbase = ntile * 128;
        #pragma unroll
        for (int m_ = 0; m_ < 4; m_++) {
            const int n0 = wn + m_ * 16 + g;
            const float dn0 = g_deg[b * N_DIM + nbase + n0];
            const float dn1 = g_deg[b * N_DIM + nbase + n0 + 8];
            #pragma unroll
            for (int n_ = 0; n_ < 8; n_++) {
                const int f0 = wf + n_ * 8 + 2 * t4;
                const float bi0 = bias[f0], bi1 = bias[f0 + 1];
                const float p00 = acc[m_][n_][0] + Cs[(n0    ) * K3_RPAD + f0    ];
                const float p10 = acc[m_][n_][1] + Cs[(n0    ) * K3_RPAD + f0 + 1];
                const float p01 = acc[m_][n_][2] + Cs[(n0 + 8) * K3_RPAD + f0    ];
                const float p11 = acc[m_][n_][3] + Cs[(n0 + 8) * K3_RPAD + f0 + 1];
                const float2 s0 = *reinterpret_cast<const float2*>(
                    Yb + (size_t)(nbase + n0) * F_DIM + f0);
                const float2 s1 = *reinterpret_cast<const float2*>(
                    Yb + (size_t)(nbase + n0 + 8) * F_DIM + f0);
                float2 v0, v1;
                v0.x = dn0 * (p00 + s0.x) + bi0;
                v0.y = dn0 * (p10 + s0.y) + bi1;
                v1.x = dn1 * (p01 + s1.x) + bi0;
                v1.y = dn1 * (p11 + s1.y) + bi1;
                *reinterpret_cast<float2*>(out + ((size_t)b * N_DIM + nbase + n0    ) * F_DIM + f0) = v0;
                *reinterpret_cast<float2*>(out + ((size_t)b * N_DIM + nbase + n0 + 8) * F_DIM + f0) = v1;
            }
        }
    }
}

// ---------------------------------------------------------------------------
extern "C" void kernel_launch(void* const* d_in, const int* in_sizes, int n_in,
                              void* d_out, int out_size) {
    const float* x    = (const float*)d_in[0];   // [8,2048,128]
    const float* adj  = (const float*)d_in[1];   // [8,2048,2048]
    const float* W    = (const float*)d_in[2];   // [128,128]
    const float* bias = (const float*)d_in[3];   // [128]
    float* out = (float*)d_out;                  // [8,2048,128]

    cudaFuncSetAttribute(gcn_xw_kernel,  cudaFuncAttributeMaxDynamicSharedMemorySize, K2_SMEM);
    cudaFuncSetAttribute(gcn_agg_kernel, cudaFuncAttributeMaxDynamicSharedMemorySize, K3_SMEM);

    gcn_deg_kernel<<<(B_DIM * N_DIM) / 8, 256>>>(adj);
    gcn_xw_kernel<<<dim3(N_DIM / 128, B_DIM), 128, K2_SMEM>>>(x, W);
    gcn_agg_kernel<<<dim3(N_DIM / 128, B_DIM), 256, K3_SMEM>>>(adj, bias, out);
}